// round 1
// baseline (speedup 1.0000x reference)
#include <cuda_runtime.h>
#include <math.h>

#define NC 50000
#define NG 2000
#define D  64
#define NE 1000000
#define NP 500000
#define W3 (1.0f/3.0f)
#define BN_EPS 1e-5f

// ---------------- scratch (static device globals; no runtime alloc) -------
__device__ int   d_deg_src1[NC], d_deg_src2[NC];
__device__ int   d_deg_dst1[NG], d_deg_dst2[NG];
__device__ int   d_cur_c1[NC],   d_cur_c2[NC];
__device__ int   d_cur_g1[NG],   d_cur_g2[NG];
__device__ float d_cj1[NC], d_cj2[NC], d_ci1[NG], d_ci2[NG];
__device__ int   d_off_g1[NG+1], d_off_g2[NG+1];
__device__ int   d_off_c1[NC+1], d_off_c2[NC+1];
__device__ int   d_csr_g1[NE], d_csr_g2[NE];   // src lists grouped by dst (gene)
__device__ int   d_csr_c1[NE], d_csr_c2[NE];   // dst lists grouped by src (cell)
__device__ float d_gA[NG*D], d_ih[NG*D];
__device__ float d_c1A[NC*D], d_c2A[NC*D];
__device__ float d_u1[NC*D],  d_u2[NC*D];
__device__ float d_uf1[NC*D], d_uf2[NC*D];

// ---------------- setup kernels -------------------------------------------
__global__ void zero_kernel() {
    int i = blockIdx.x * blockDim.x + threadIdx.x;
    if (i < NC) { d_deg_src1[i]=0; d_deg_src2[i]=0; d_cur_c1[i]=0; d_cur_c2[i]=0; }
    if (i < NG) { d_deg_dst1[i]=0; d_deg_dst2[i]=0; d_cur_g1[i]=0; d_cur_g2[i]=0; }
}

__global__ void hist_kernel(const int* __restrict__ s1, const int* __restrict__ t1,
                            const int* __restrict__ s2, const int* __restrict__ t2) {
    int i = blockIdx.x * blockDim.x + threadIdx.x;
    if (i < NE) {
        atomicAdd(&d_deg_src1[s1[i]], 1);
        atomicAdd(&d_deg_dst1[t1[i]], 1);
        atomicAdd(&d_deg_src2[s2[i]], 1);
        atomicAdd(&d_deg_dst2[t2[i]], 1);
    }
}

__global__ void invsqrt_kernel() {
    int i = blockIdx.x * blockDim.x + threadIdx.x;
    if (i < NC) {
        int a = d_deg_src1[i]; d_cj1[i] = a > 0 ? rsqrtf((float)a) : 0.f;
        int b = d_deg_src2[i]; d_cj2[i] = b > 0 ? rsqrtf((float)b) : 0.f;
    }
    if (i < NG) {
        int a = d_deg_dst1[i]; d_ci1[i] = a > 0 ? rsqrtf((float)a) : 0.f;
        int b = d_deg_dst2[i]; d_ci2[i] = b > 0 ? rsqrtf((float)b) : 0.f;
    }
}

// 4 independent exclusive scans, one block each. blockDim = 1024.
__global__ void scan4_kernel() {
    const int* in; int* out; int n;
    switch (blockIdx.x) {
        case 0:  in = d_deg_dst1; out = d_off_g1; n = NG; break;
        case 1:  in = d_deg_dst2; out = d_off_g2; n = NG; break;
        case 2:  in = d_deg_src1; out = d_off_c1; n = NC; break;
        default: in = d_deg_src2; out = d_off_c2; n = NC; break;
    }
    __shared__ int warp_sums[32];
    __shared__ int s_carry;
    int tid = threadIdx.x;
    if (tid == 0) s_carry = 0;
    __syncthreads();
    for (int base = 0; base < n; base += 1024) {
        int i = base + tid;
        int v = (i < n) ? in[i] : 0;
        int x = v;
        #pragma unroll
        for (int dlt = 1; dlt < 32; dlt <<= 1) {
            int y = __shfl_up_sync(0xffffffffu, x, dlt);
            if ((tid & 31) >= dlt) x += y;
        }
        if ((tid & 31) == 31) warp_sums[tid >> 5] = x;
        __syncthreads();
        if (tid < 32) {
            int y = warp_sums[tid];
            int z = y;
            #pragma unroll
            for (int dlt = 1; dlt < 32; dlt <<= 1) {
                int t = __shfl_up_sync(0xffffffffu, z, dlt);
                if (tid >= dlt) z += t;
            }
            warp_sums[tid] = z - y;   // exclusive offset of warp
        }
        __syncthreads();
        int incl = x + warp_sums[tid >> 5];
        int carry = s_carry;
        if (i < n) out[i] = carry + incl - v;   // exclusive
        __syncthreads();
        if (tid == 1023) s_carry = carry + incl;  // chunk total (OOB lanes were 0)
        __syncthreads();
    }
    if (tid == 0) out[n] = s_carry;
}

__global__ void build_kernel(const int* __restrict__ s1, const int* __restrict__ t1,
                             const int* __restrict__ s2, const int* __restrict__ t2) {
    int i = blockIdx.x * blockDim.x + threadIdx.x;
    if (i >= NE) return;
    int s = s1[i], d = t1[i];
    d_csr_g1[d_off_g1[d] + atomicAdd(&d_cur_g1[d], 1)] = s;
    d_csr_c1[d_off_c1[s] + atomicAdd(&d_cur_c1[s], 1)] = d;
    s = s2[i]; d = t2[i];
    d_csr_g2[d_off_g2[d] + atomicAdd(&d_cur_g2[d], 1)] = s;
    d_csr_c2[d_off_c2[s] + atomicAdd(&d_cur_c2[s], 1)] = d;
}

__global__ void init_kernel(const float* __restrict__ cf1, const float* __restrict__ cf2,
                            const float* __restrict__ gf) {
    int i = blockIdx.x * blockDim.x + threadIdx.x;
    if (i < NC * D) { d_u1[i] = W3 * cf1[i]; d_u2[i] = W3 * cf2[i]; }
    if (i < NG * D) { d_ih[i] = W3 * gf[i]; }
}

// ---------------- SpMM (gather-only, CSR) ----------------------------------
// one gene per block, 64 threads (one per feature dim)
__global__ void gene_spmm_kernel(const float* __restrict__ C1in,
                                 const float* __restrict__ C2in, int layer) {
    if (layer) { C1in = d_c1A; C2in = d_c2A; }
    const int i = blockIdx.x;
    const int tid = threadIdx.x;
    const int CH = 128;
    __shared__ int   sI[CH];
    __shared__ float sW[CH];
    float acc1 = 0.f, acc2 = 0.f;

    int beg = d_off_g1[i], end = d_off_g1[i+1];
    for (int b = beg; b < end; b += CH) {
        int m = min(CH, end - b);
        __syncthreads();
        for (int t = tid; t < m; t += 64) { int s = d_csr_g1[b+t]; sI[t] = s; sW[t] = d_cj1[s]; }
        __syncthreads();
        #pragma unroll 4
        for (int k = 0; k < m; k++)
            acc1 = fmaf(sW[k], __ldg(&C1in[sI[k]*D + tid]), acc1);
    }
    beg = d_off_g2[i]; end = d_off_g2[i+1];
    for (int b = beg; b < end; b += CH) {
        int m = min(CH, end - b);
        __syncthreads();
        for (int t = tid; t < m; t += 64) { int s = d_csr_g2[b+t]; sI[t] = s; sW[t] = d_cj2[s]; }
        __syncthreads();
        #pragma unroll 4
        for (int k = 0; k < m; k++)
            acc2 = fmaf(sW[k], __ldg(&C2in[sI[k]*D + tid]), acc2);
    }
    float g = 0.5f * (d_ci1[i]*acc1 + d_ci2[i]*acc2);
    if (!layer) d_gA[i*D + tid] = g;
    d_ih[i*D + tid] += W3 * g;
}

// one cell per block, 64 threads
__global__ void cell_spmm_kernel(const float* __restrict__ Gin, int layer) {
    if (layer) Gin = d_gA;
    const int j = blockIdx.x;
    const int tid = threadIdx.x;
    const int CH = 64;
    __shared__ int   sI[CH];
    __shared__ float sW[CH];
    float acc1 = 0.f, acc2 = 0.f;

    int beg = d_off_c1[j], end = d_off_c1[j+1];
    for (int b = beg; b < end; b += CH) {
        int m = min(CH, end - b);
        __syncthreads();
        if (tid < m) { int dd = d_csr_c1[b+tid]; sI[tid] = dd; sW[tid] = d_ci1[dd]; }
        __syncthreads();
        #pragma unroll 4
        for (int k = 0; k < m; k++)
            acc1 = fmaf(sW[k], __ldg(&Gin[sI[k]*D + tid]), acc1);
    }
    beg = d_off_c2[j]; end = d_off_c2[j+1];
    for (int b = beg; b < end; b += CH) {
        int m = min(CH, end - b);
        __syncthreads();
        if (tid < m) { int dd = d_csr_c2[b+tid]; sI[tid] = dd; sW[tid] = d_ci2[dd]; }
        __syncthreads();
        #pragma unroll 4
        for (int k = 0; k < m; k++)
            acc2 = fmaf(sW[k], __ldg(&Gin[sI[k]*D + tid]), acc2);
    }
    float v1 = d_cj1[j] * acc1;
    float v2 = d_cj2[j] * acc2;
    if (!layer) { d_c1A[j*D + tid] = v1; d_c2A[j*D + tid] = v2; }
    d_u1[j*D + tid] += W3 * v1;
    d_u2[j*D + tid] += W3 * v2;
}

// ---------------- embed: y = ELU(BN(u @ W[:64] + b + W[64+branch])) --------
// block = 256 threads, 64 rows per block, blockIdx.y = branch
__global__ void emb_kernel(const float* __restrict__ Wm, const float* __restrict__ bb,
                           const float* __restrict__ gam, const float* __restrict__ bet,
                           const float* __restrict__ mu,  const float* __restrict__ var) {
    const int branch = blockIdx.y;
    const float* __restrict__ U  = branch ? d_u2  : d_u1;
    float* __restrict__ UF       = branch ? d_uf2 : d_uf1;

    __shared__ float sU[64][65];
    __shared__ float sW[64][64];
    int tid = threadIdx.x;
    int row0 = blockIdx.x * 64;

    for (int t = tid; t < 64*64; t += 256) sW[t/64][t%64] = Wm[t];
    for (int t = tid; t < 64*64; t += 256) {
        int r = t / 64, k = t % 64;
        int gr = row0 + r;
        sU[r][k] = (gr < NC) ? U[gr*D + k] : 0.f;
    }
    __syncthreads();

    int c  = tid & 63;
    int rq = tid >> 6;       // 0..3, each owns 16 rows
    float acc[16];
    #pragma unroll
    for (int rr = 0; rr < 16; rr++) acc[rr] = 0.f;
    #pragma unroll 8
    for (int k = 0; k < 64; k++) {
        float w = sW[k][c];
        #pragma unroll
        for (int rr = 0; rr < 16; rr++)
            acc[rr] = fmaf(sU[rq*16 + rr][k], w, acc[rr]);
    }
    float scale = gam[c] * rsqrtf(var[c] + BN_EPS);
    float shift = bet[c] - mu[c] * scale;
    float beff  = bb[c] + Wm[(64 + branch)*64 + c];
    #pragma unroll
    for (int rr = 0; rr < 16; rr++) {
        int r = row0 + rq*16 + rr;
        if (r < NC) {
            float y = (acc[rr] + beff) * scale + shift;
            UF[r*D + c] = y > 0.f ? y : expm1f(y);
        }
    }
}

// ---------------- decoder: warp per positive edge --------------------------
__global__ void dot_kernel(const int* __restrict__ ps1, const int* __restrict__ pd1,
                           const int* __restrict__ ps2, const int* __restrict__ pd2,
                           float* __restrict__ out) {
    int t    = blockIdx.x * blockDim.x + threadIdx.x;
    int gw   = t >> 5;
    int lane = t & 31;
    if (gw >= 2*NP) return;
    const float* uf; int s, d;
    if (gw < NP) { uf = d_uf1; s = __ldg(&ps1[gw]);    d = __ldg(&pd1[gw]); }
    else         { uf = d_uf2; int e = gw - NP; s = __ldg(&ps2[e]); d = __ldg(&pd2[e]); }
    float2 a = *(const float2*)(uf   + s*D + lane*2);
    float2 b = *(const float2*)(d_ih + d*D + lane*2);
    float v = a.x*b.x + a.y*b.y;
    #pragma unroll
    for (int o = 16; o; o >>= 1) v += __shfl_down_sync(0xffffffffu, v, o);
    if (lane == 0) out[gw] = v;
}

// ---------------- host ------------------------------------------------------
extern "C" void kernel_launch(void* const* d_in, const int* in_sizes, int n_in,
                              void* d_out, int out_size) {
    const float* cf1 = (const float*)d_in[0];
    const float* cf2 = (const float*)d_in[1];
    const float* gf  = (const float*)d_in[2];
    const float* Wm  = (const float*)d_in[3];
    const float* bb  = (const float*)d_in[4];
    const float* gam = (const float*)d_in[5];
    const float* bet = (const float*)d_in[6];
    const float* mu  = (const float*)d_in[7];
    const float* var = (const float*)d_in[8];
    const int* es1 = (const int*)d_in[9];
    const int* ed1 = (const int*)d_in[10];
    const int* es2 = (const int*)d_in[11];
    const int* ed2 = (const int*)d_in[12];
    const int* ps1 = (const int*)d_in[13];
    const int* pd1 = (const int*)d_in[14];
    const int* ps2 = (const int*)d_in[15];
    const int* pd2 = (const int*)d_in[16];
    float* out = (float*)d_out;

    zero_kernel   <<<(NC + 255)/256, 256>>>();
    hist_kernel   <<<(NE + 255)/256, 256>>>(es1, ed1, es2, ed2);
    invsqrt_kernel<<<(NC + 255)/256, 256>>>();
    scan4_kernel  <<<4, 1024>>>();
    build_kernel  <<<(NE + 255)/256, 256>>>(es1, ed1, es2, ed2);
    init_kernel   <<<(NC*D + 255)/256, 256>>>(cf1, cf2, gf);

    // layer 1 (reads inputs, writes g/c buffers + accumulators)
    gene_spmm_kernel<<<NG, 64>>>(cf1, cf2, 0);
    cell_spmm_kernel<<<NC, 64>>>(gf, 0);
    // layer 2 (reads layer-1 buffers, only accumulators needed)
    gene_spmm_kernel<<<NG, 64>>>(nullptr, nullptr, 1);
    cell_spmm_kernel<<<NC, 64>>>(nullptr, 1);

    emb_kernel<<<dim3((NC + 63)/64, 2), 256>>>(Wm, bb, gam, bet, mu, var);
    dot_kernel<<<(2*NP*32 + 255)/256, 256>>>(ps1, pd1, ps2, pd2, out);
}

// round 3
// speedup vs baseline: 1.2684x; 1.2684x over previous
#include <cuda_runtime.h>
#include <math.h>

#define NC 50000
#define NG 2000
#define D  64
#define NE 1000000
#define NP 500000
#define W3 (1.0f/3.0f)
#define BN_EPS 1e-5f

// ---------------- scratch (static device globals) --------------------------
__device__ int   d_deg_src1[NC], d_deg_src2[NC];
__device__ int   d_deg_dst1[NG], d_deg_dst2[NG];
__device__ int   d_off_c1[NC], d_off_c2[NC];
__device__ int   d_off_g1[NG], d_off_g2[NG];
__device__ int   d_cur_c1[NC], d_cur_c2[NC];
__device__ int   d_cur_g1[NG], d_cur_g2[NG];
__device__ float d_cj1[NC], d_cj2[NC], d_ci1[NG], d_ci2[NG];
__device__ int   d_ctr[4];
__device__ int   d_csr_g1[NE], d_csr_g2[NE];   // cell lists grouped by gene
__device__ int   d_csr_c1[NE], d_csr_c2[NE];   // gene lists grouped by cell
__device__ float d_gA[NG*D], d_ih[NG*D];
__device__ float d_c1A[NC*D], d_c2A[NC*D];
__device__ float d_u1[NC*D],  d_u2[NC*D];
__device__ float d_uf1[NC*D], d_uf2[NC*D];

// ---------------- setup -----------------------------------------------------
__global__ void zero_kernel() {
    int i = blockIdx.x * blockDim.x + threadIdx.x;
    if (i < NC) { d_deg_src1[i]=0; d_deg_src2[i]=0; }
    if (i < NG) { d_deg_dst1[i]=0; d_deg_dst2[i]=0; }
    if (i < 4)  d_ctr[i] = 0;
}

// 4 edges per thread via int4
__global__ void hist_kernel(const int4* __restrict__ s1, const int4* __restrict__ t1,
                            const int4* __restrict__ s2, const int4* __restrict__ t2) {
    int i = blockIdx.x * blockDim.x + threadIdx.x;
    if (i >= NE/4) return;
    int4 a = __ldg(&s1[i]), b = __ldg(&t1[i]);
    int4 c = __ldg(&s2[i]), e = __ldg(&t2[i]);
    atomicAdd(&d_deg_src1[a.x],1); atomicAdd(&d_deg_src1[a.y],1);
    atomicAdd(&d_deg_src1[a.z],1); atomicAdd(&d_deg_src1[a.w],1);
    atomicAdd(&d_deg_dst1[b.x],1); atomicAdd(&d_deg_dst1[b.y],1);
    atomicAdd(&d_deg_dst1[b.z],1); atomicAdd(&d_deg_dst1[b.w],1);
    atomicAdd(&d_deg_src2[c.x],1); atomicAdd(&d_deg_src2[c.y],1);
    atomicAdd(&d_deg_src2[c.z],1); atomicAdd(&d_deg_src2[c.w],1);
    atomicAdd(&d_deg_dst2[e.x],1); atomicAdd(&d_deg_dst2[e.y],1);
    atomicAdd(&d_deg_dst2[e.z],1); atomicAdd(&d_deg_dst2[e.w],1);
}

// warp-aggregated range allocation (CSR segments need not be in index order)
__device__ __forceinline__ int warp_alloc(int v, int* ctr, int lane) {
    int x = v;
    #pragma unroll
    for (int d = 1; d < 32; d <<= 1) {
        int y = __shfl_up_sync(0xffffffffu, x, d);
        if (lane >= d) x += y;
    }
    int tot = __shfl_sync(0xffffffffu, x, 31);
    int base = 0;
    if (lane == 31) base = atomicAdd(ctr, tot);
    base = __shfl_sync(0xffffffffu, base, 31);
    return base + x - v;  // exclusive within warp + global base
}

__global__ void prep_kernel() {
    int i = blockIdx.x * blockDim.x + threadIdx.x;
    int lane = threadIdx.x & 31;
    // cells
    int dg1 = (i < NC) ? d_deg_src1[i] : 0;
    int dg2 = (i < NC) ? d_deg_src2[i] : 0;
    int o1 = warp_alloc(dg1, &d_ctr[0], lane);
    int o2 = warp_alloc(dg2, &d_ctr[1], lane);
    if (i < NC) {
        d_cj1[i] = dg1 ? rsqrtf((float)dg1) : 0.f;
        d_cj2[i] = dg2 ? rsqrtf((float)dg2) : 0.f;
        d_off_c1[i] = o1; d_cur_c1[i] = o1;
        d_off_c2[i] = o2; d_cur_c2[i] = o2;
    }
    // genes (only warps overlapping [0,NG))
    if (i - lane < NG) {
        int e1 = (i < NG) ? d_deg_dst1[i] : 0;
        int e2 = (i < NG) ? d_deg_dst2[i] : 0;
        int p1 = warp_alloc(e1, &d_ctr[2], lane);
        int p2 = warp_alloc(e2, &d_ctr[3], lane);
        if (i < NG) {
            d_ci1[i] = e1 ? rsqrtf((float)e1) : 0.f;
            d_ci2[i] = e2 ? rsqrtf((float)e2) : 0.f;
            d_off_g1[i] = p1; d_cur_g1[i] = p1;
            d_off_g2[i] = p2; d_cur_g2[i] = p2;
        }
    }
}

__global__ void build_kernel(const int4* __restrict__ s1, const int4* __restrict__ t1,
                             const int4* __restrict__ s2, const int4* __restrict__ t2) {
    int i = blockIdx.x * blockDim.x + threadIdx.x;
    if (i >= NE/4) return;
    int4 a = __ldg(&s1[i]), b = __ldg(&t1[i]);
    int4 c = __ldg(&s2[i]), e = __ldg(&t2[i]);
    int sa[4] = {a.x,a.y,a.z,a.w}, ta[4] = {b.x,b.y,b.z,b.w};
    int sc[4] = {c.x,c.y,c.z,c.w}, tc[4] = {e.x,e.y,e.z,e.w};
    #pragma unroll
    for (int k = 0; k < 4; k++) {
        d_csr_g1[atomicAdd(&d_cur_g1[ta[k]], 1)] = sa[k];
        d_csr_c1[atomicAdd(&d_cur_c1[sa[k]], 1)] = ta[k];
        d_csr_g2[atomicAdd(&d_cur_g2[tc[k]], 1)] = sc[k];
        d_csr_c2[atomicAdd(&d_cur_c2[sc[k]], 1)] = tc[k];
    }
}

__global__ void init_kernel(const float4* __restrict__ cf1, const float4* __restrict__ cf2,
                            const float4* __restrict__ gf) {
    int i = blockIdx.x * blockDim.x + threadIdx.x;
    if (i < NC*D/4) {
        float4 a = __ldg(&cf1[i]), b = __ldg(&cf2[i]);
        a.x*=W3; a.y*=W3; a.z*=W3; a.w*=W3;
        b.x*=W3; b.y*=W3; b.z*=W3; b.w*=W3;
        ((float4*)d_u1)[i] = a; ((float4*)d_u2)[i] = b;
    }
    if (i < NG*D/4) {
        float4 g = __ldg(&gf[i]);
        g.x*=W3; g.y*=W3; g.z*=W3; g.w*=W3;
        ((float4*)d_ih)[i] = g;
    }
}

// ---------------- SpMM: warp-centric gather --------------------------------
// block = 128 threads (4 warps) per gene: warps {0,1}->rel1 halves, {2,3}->rel2
// layer=0: inputs are the kernel args; layer=1: inputs are device globals
// (NOTE: device-global addresses must be taken in DEVICE code — GB300's ATS
//  makes host-shadow addresses silently readable with wrong data.)
__global__ void gene_spmm_kernel(const float2* __restrict__ C1p,
                                 const float2* __restrict__ C2p, int layer) {
    const float2* C1 = layer ? (const float2*)d_c1A : C1p;
    const float2* C2 = layer ? (const float2*)d_c2A : C2p;
    const int g    = blockIdx.x;
    const int w    = threadIdx.x >> 5;
    const int lane = threadIdx.x & 31;
    const int rel  = w >> 1;
    const int half = w & 1;

    const int*    csr = rel ? d_csr_g2 : d_csr_g1;
    const float*  cj  = rel ? d_cj2    : d_cj1;
    const float2* C   = rel ? C2       : C1;
    const int beg = rel ? d_off_g2[g]  : d_off_g1[g];
    const int cnt = rel ? d_deg_dst2[g]: d_deg_dst1[g];

    float2 acc = make_float2(0.f, 0.f);
    for (int base = half * 32; base < cnt; base += 64) {
        int p = base + lane;
        int idx = 0; float wt = 0.f;
        if (p < cnt) { idx = __ldg(&csr[beg + p]); wt = __ldg(&cj[idx]); }
        #pragma unroll
        for (int j = 0; j < 32; j++) {
            int   bi = __shfl_sync(0xffffffffu, idx, j);
            float bw = __shfl_sync(0xffffffffu, wt,  j);
            float2 v = __ldg(&C[bi * 32 + lane]);
            acc.x = fmaf(bw, v.x, acc.x);
            acc.y = fmaf(bw, v.y, acc.y);
        }
    }
    __shared__ float2 part[4][32];
    part[w][lane] = acc;
    __syncthreads();
    if (threadIdx.x < 32) {
        float2 a0 = part[0][lane], a1 = part[1][lane];
        float2 a2 = part[2][lane], a3 = part[3][lane];
        float c1s = d_ci1[g], c2s = d_ci2[g];
        float2 go;
        go.x = 0.5f * (c1s * (a0.x + a1.x) + c2s * (a2.x + a3.x));
        go.y = 0.5f * (c1s * (a0.y + a1.y) + c2s * (a2.y + a3.y));
        if (!layer) ((float2*)d_gA)[g * 32 + lane] = go;
        float2 ih = ((float2*)d_ih)[g * 32 + lane];
        ih.x += W3 * go.x; ih.y += W3 * go.y;
        ((float2*)d_ih)[g * 32 + lane] = ih;
    }
}

// block = 256 threads = 8 warps = 4 cells x 2 relations; warps fully independent
__global__ void cell_spmm_kernel(const float2* __restrict__ Gp, int layer) {
    const float2* G = layer ? (const float2*)d_gA : Gp;
    const int c    = blockIdx.x * 4 + (threadIdx.x >> 6);
    const int rel  = (threadIdx.x >> 5) & 1;
    const int lane = threadIdx.x & 31;
    if (c >= NC) return;

    const int*   csr = rel ? d_csr_c2 : d_csr_c1;
    const float* ci  = rel ? d_ci2    : d_ci1;
    const int beg = rel ? d_off_c2[c]  : d_off_c1[c];
    const int cnt = rel ? d_deg_src2[c]: d_deg_src1[c];

    float2 acc = make_float2(0.f, 0.f);
    for (int base = 0; base < cnt; base += 32) {
        int p = base + lane;
        int idx = 0; float wt = 0.f;
        if (p < cnt) { idx = __ldg(&csr[beg + p]); wt = __ldg(&ci[idx]); }
        #pragma unroll
        for (int j = 0; j < 32; j++) {
            int   bi = __shfl_sync(0xffffffffu, idx, j);
            float bw = __shfl_sync(0xffffffffu, wt,  j);
            float2 v = __ldg(&G[bi * 32 + lane]);
            acc.x = fmaf(bw, v.x, acc.x);
            acc.y = fmaf(bw, v.y, acc.y);
        }
    }
    float s = rel ? d_cj2[c] : d_cj1[c];
    acc.x *= s; acc.y *= s;
    if (!layer) {
        float2* tgt = rel ? (float2*)d_c2A : (float2*)d_c1A;
        tgt[c * 32 + lane] = acc;
    }
    float2* u = rel ? (float2*)d_u2 : (float2*)d_u1;
    float2 uv = u[c * 32 + lane];
    uv.x += W3 * acc.x; uv.y += W3 * acc.y;
    u[c * 32 + lane] = uv;
}

// ---------------- embed: y = ELU(BN(u @ W[:64] + b + W[64+branch])) --------
__global__ void emb_kernel(const float* __restrict__ Wm, const float* __restrict__ bb,
                           const float* __restrict__ gam, const float* __restrict__ bet,
                           const float* __restrict__ mu,  const float* __restrict__ var) {
    const int branch = blockIdx.y;
    const float* __restrict__ U  = branch ? d_u2  : d_u1;
    float* __restrict__ UF       = branch ? d_uf2 : d_uf1;

    __shared__ float sU[64][65];
    __shared__ float sW[64][64];
    int tid = threadIdx.x;
    int row0 = blockIdx.x * 64;

    for (int t = tid; t < 64*64; t += 256) sW[t/64][t%64] = Wm[t];
    for (int t = tid; t < 64*64; t += 256) {
        int r = t / 64, k = t % 64;
        int gr = row0 + r;
        sU[r][k] = (gr < NC) ? U[gr*D + k] : 0.f;
    }
    __syncthreads();

    int c  = tid & 63;
    int rq = tid >> 6;
    float acc[16];
    #pragma unroll
    for (int rr = 0; rr < 16; rr++) acc[rr] = 0.f;
    #pragma unroll 8
    for (int k = 0; k < 64; k++) {
        float w = sW[k][c];
        #pragma unroll
        for (int rr = 0; rr < 16; rr++)
            acc[rr] = fmaf(sU[rq*16 + rr][k], w, acc[rr]);
    }
    float scale = gam[c] * rsqrtf(var[c] + BN_EPS);
    float shift = bet[c] - mu[c] * scale;
    float beff  = bb[c] + Wm[(64 + branch)*64 + c];
    #pragma unroll
    for (int rr = 0; rr < 16; rr++) {
        int r = row0 + rq*16 + rr;
        if (r < NC) {
            float y = (acc[rr] + beff) * scale + shift;
            UF[r*D + c] = y > 0.f ? y : expm1f(y);
        }
    }
}

// ---------------- decoder: 16 lanes per edge, float4 ----------------------
__global__ void dot_kernel(const int* __restrict__ ps1, const int* __restrict__ pd1,
                           const int* __restrict__ ps2, const int* __restrict__ pd2,
                           float* __restrict__ out) {
    int t = blockIdx.x * blockDim.x + threadIdx.x;
    int e = t >> 4;
    int l = t & 15;
    if (e >= 2*NP) return;
    const float4* uf; int s, d;
    if (e < NP) { uf = (const float4*)d_uf1; s = __ldg(&ps1[e]); d = __ldg(&pd1[e]); }
    else { int e2 = e - NP; uf = (const float4*)d_uf2; s = __ldg(&ps2[e2]); d = __ldg(&pd2[e2]); }
    float4 a = __ldg(&uf[s * 16 + l]);
    float4 b = __ldg(&((const float4*)d_ih)[d * 16 + l]);
    float v = a.x*b.x + a.y*b.y + a.z*b.z + a.w*b.w;
    v += __shfl_xor_sync(0xffffffffu, v, 8);
    v += __shfl_xor_sync(0xffffffffu, v, 4);
    v += __shfl_xor_sync(0xffffffffu, v, 2);
    v += __shfl_xor_sync(0xffffffffu, v, 1);
    if (l == 0) out[e] = v;
}

// ---------------- host ------------------------------------------------------
extern "C" void kernel_launch(void* const* d_in, const int* in_sizes, int n_in,
                              void* d_out, int out_size) {
    const float* cf1 = (const float*)d_in[0];
    const float* cf2 = (const float*)d_in[1];
    const float* gf  = (const float*)d_in[2];
    const float* Wm  = (const float*)d_in[3];
    const float* bb  = (const float*)d_in[4];
    const float* gam = (const float*)d_in[5];
    const float* bet = (const float*)d_in[6];
    const float* mu  = (const float*)d_in[7];
    const float* var = (const float*)d_in[8];
    const int* es1 = (const int*)d_in[9];
    const int* ed1 = (const int*)d_in[10];
    const int* es2 = (const int*)d_in[11];
    const int* ed2 = (const int*)d_in[12];
    const int* ps1 = (const int*)d_in[13];
    const int* pd1 = (const int*)d_in[14];
    const int* ps2 = (const int*)d_in[15];
    const int* pd2 = (const int*)d_in[16];
    float* out = (float*)d_out;

    zero_kernel <<<(NC + 255)/256, 256>>>();
    hist_kernel <<<(NE/4 + 255)/256, 256>>>((const int4*)es1, (const int4*)ed1,
                                            (const int4*)es2, (const int4*)ed2);
    prep_kernel <<<(NC + 255)/256, 256>>>();
    build_kernel<<<(NE/4 + 255)/256, 256>>>((const int4*)es1, (const int4*)ed1,
                                            (const int4*)es2, (const int4*)ed2);
    init_kernel <<<(NC*D/4 + 255)/256, 256>>>((const float4*)cf1, (const float4*)cf2,
                                              (const float4*)gf);

    // layer 1 (reads harness inputs)
    gene_spmm_kernel<<<NG, 128>>>((const float2*)cf1, (const float2*)cf2, 0);
    cell_spmm_kernel<<<(NC + 3)/4, 256>>>((const float2*)gf, 0);
    // layer 2 (reads device-global intermediates, selected in device code)
    gene_spmm_kernel<<<NG, 128>>>(nullptr, nullptr, 1);
    cell_spmm_kernel<<<(NC + 3)/4, 256>>>(nullptr, 1);

    emb_kernel<<<dim3((NC + 63)/64, 2), 256>>>(Wm, bb, gam, bet, mu, var);
    dot_kernel<<<(2*NP*16 + 255)/256, 256>>>(ps1, pd1, ps2, pd2, out);
}

// round 4
// speedup vs baseline: 1.5453x; 1.2183x over previous
#include <cuda_runtime.h>
#include <math.h>

#define NC 50000
#define NG 2000
#define D  64
#define NE 1000000
#define NP 500000
#define W3 (1.0f/3.0f)
#define BN_EPS 1e-5f

// ---------------- scratch (static device globals) --------------------------
__device__ int   d_deg_src1[NC], d_deg_src2[NC];
__device__ int   d_deg_dst1[NG], d_deg_dst2[NG];
__device__ int   d_off_c1[NC], d_off_c2[NC];
__device__ int   d_off_g1[NG], d_off_g2[NG];
__device__ float d_cj1[NC], d_cj2[NC], d_ci1[NG], d_ci2[NG];
__device__ int   d_ctr[4];
__device__ int   d_rk_c1[NE], d_rk_c2[NE], d_rk_g1[NE], d_rk_g2[NE];
__device__ int   d_csr_g1[NE], d_csr_g2[NE];   // cell ids grouped by gene
__device__ int   d_csr_c1[NE], d_csr_c2[NE];   // gene ids grouped by cell
// pre-scaled feature tables (+1 zero dummy row each)
__device__ float d_s1a[(NC+1)*D], d_s2a[(NC+1)*D];   // cj * cell feats, layer in
__device__ float d_s1b[(NC+1)*D], d_s2b[(NC+1)*D];   // cj * cell feats, layer1 out
__device__ float d_sg1a[(NG+1)*D], d_sg2a[(NG+1)*D]; // ci * gene feats, layer in
__device__ float d_sg1b[(NG+1)*D], d_sg2b[(NG+1)*D]; // ci * gene feats, layer1 out
__device__ float d_ih[NG*D];
__device__ float d_u1[NC*D],  d_u2[NC*D];
__device__ float d_uf1[NC*D], d_uf2[NC*D];

// ---------------- setup -----------------------------------------------------
__global__ void zero_kernel() {
    int i = blockIdx.x * blockDim.x + threadIdx.x;
    if (i < NC) { d_deg_src1[i]=0; d_deg_src2[i]=0; }
    if (i < NG) { d_deg_dst1[i]=0; d_deg_dst2[i]=0; }
    if (i < 4)  d_ctr[i] = 0;
    if (i < 16) {  // zero the dummy rows (float4 granularity)
        ((float4*)&d_s1a[NC*D])[i]  = make_float4(0,0,0,0);
        ((float4*)&d_s2a[NC*D])[i]  = make_float4(0,0,0,0);
        ((float4*)&d_s1b[NC*D])[i]  = make_float4(0,0,0,0);
        ((float4*)&d_s2b[NC*D])[i]  = make_float4(0,0,0,0);
        ((float4*)&d_sg1a[NG*D])[i] = make_float4(0,0,0,0);
        ((float4*)&d_sg2a[NG*D])[i] = make_float4(0,0,0,0);
        ((float4*)&d_sg1b[NG*D])[i] = make_float4(0,0,0,0);
        ((float4*)&d_sg2b[NG*D])[i] = make_float4(0,0,0,0);
    }
}

// single atomic pass: counters + per-edge ranks (rank stores are coalesced int4)
__global__ void hist_kernel(const int4* __restrict__ s1, const int4* __restrict__ t1,
                            const int4* __restrict__ s2, const int4* __restrict__ t2) {
    int i = blockIdx.x * blockDim.x + threadIdx.x;
    if (i >= NE/4) return;
    int4 a = __ldg(&s1[i]), b = __ldg(&t1[i]);
    int4 c = __ldg(&s2[i]), e = __ldg(&t2[i]);
    int4 r;
    r.x = atomicAdd(&d_deg_src1[a.x],1); r.y = atomicAdd(&d_deg_src1[a.y],1);
    r.z = atomicAdd(&d_deg_src1[a.z],1); r.w = atomicAdd(&d_deg_src1[a.w],1);
    ((int4*)d_rk_c1)[i] = r;
    r.x = atomicAdd(&d_deg_dst1[b.x],1); r.y = atomicAdd(&d_deg_dst1[b.y],1);
    r.z = atomicAdd(&d_deg_dst1[b.z],1); r.w = atomicAdd(&d_deg_dst1[b.w],1);
    ((int4*)d_rk_g1)[i] = r;
    r.x = atomicAdd(&d_deg_src2[c.x],1); r.y = atomicAdd(&d_deg_src2[c.y],1);
    r.z = atomicAdd(&d_deg_src2[c.z],1); r.w = atomicAdd(&d_deg_src2[c.w],1);
    ((int4*)d_rk_c2)[i] = r;
    r.x = atomicAdd(&d_deg_dst2[e.x],1); r.y = atomicAdd(&d_deg_dst2[e.y],1);
    r.z = atomicAdd(&d_deg_dst2[e.z],1); r.w = atomicAdd(&d_deg_dst2[e.w],1);
    ((int4*)d_rk_g2)[i] = r;
}

// warp-aggregated range allocation (CSR segments need not be in index order)
__device__ __forceinline__ int warp_alloc(int v, int* ctr, int lane) {
    int x = v;
    #pragma unroll
    for (int d = 1; d < 32; d <<= 1) {
        int y = __shfl_up_sync(0xffffffffu, x, d);
        if (lane >= d) x += y;
    }
    int tot = __shfl_sync(0xffffffffu, x, 31);
    int base = 0;
    if (lane == 31) base = atomicAdd(ctr, tot);
    base = __shfl_sync(0xffffffffu, base, 31);
    return base + x - v;
}

__global__ void prep_kernel() {
    int i = blockIdx.x * blockDim.x + threadIdx.x;
    int lane = threadIdx.x & 31;
    int dg1 = (i < NC) ? d_deg_src1[i] : 0;
    int dg2 = (i < NC) ? d_deg_src2[i] : 0;
    int o1 = warp_alloc(dg1, &d_ctr[0], lane);
    int o2 = warp_alloc(dg2, &d_ctr[1], lane);
    if (i < NC) {
        d_cj1[i] = dg1 ? rsqrtf((float)dg1) : 0.f;
        d_cj2[i] = dg2 ? rsqrtf((float)dg2) : 0.f;
        d_off_c1[i] = o1;
        d_off_c2[i] = o2;
    }
    if (i - lane < NG) {
        int e1 = (i < NG) ? d_deg_dst1[i] : 0;
        int e2 = (i < NG) ? d_deg_dst2[i] : 0;
        int p1 = warp_alloc(e1, &d_ctr[2], lane);
        int p2 = warp_alloc(e2, &d_ctr[3], lane);
        if (i < NG) {
            d_ci1[i] = e1 ? rsqrtf((float)e1) : 0.f;
            d_ci2[i] = e2 ? rsqrtf((float)e2) : 0.f;
            d_off_g1[i] = p1;
            d_off_g2[i] = p2;
        }
    }
}

// atomic-free scatter: slot = off[node] + precomputed rank
__global__ void scatter_kernel(const int4* __restrict__ s1, const int4* __restrict__ t1,
                               const int4* __restrict__ s2, const int4* __restrict__ t2) {
    int i = blockIdx.x * blockDim.x + threadIdx.x;
    if (i >= NE/4) return;
    int4 a = __ldg(&s1[i]), b = __ldg(&t1[i]);
    int4 c = __ldg(&s2[i]), e = __ldg(&t2[i]);
    int4 rc1 = __ldg(&((const int4*)d_rk_c1)[i]);
    int4 rg1 = __ldg(&((const int4*)d_rk_g1)[i]);
    int4 rc2 = __ldg(&((const int4*)d_rk_c2)[i]);
    int4 rg2 = __ldg(&((const int4*)d_rk_g2)[i]);
    int sa[4] = {a.x,a.y,a.z,a.w}, ta[4] = {b.x,b.y,b.z,b.w};
    int sc[4] = {c.x,c.y,c.z,c.w}, tc[4] = {e.x,e.y,e.z,e.w};
    int kc1[4] = {rc1.x,rc1.y,rc1.z,rc1.w}, kg1[4] = {rg1.x,rg1.y,rg1.z,rg1.w};
    int kc2[4] = {rc2.x,rc2.y,rc2.z,rc2.w}, kg2[4] = {rg2.x,rg2.y,rg2.z,rg2.w};
    #pragma unroll
    for (int k = 0; k < 4; k++) {
        d_csr_c1[__ldg(&d_off_c1[sa[k]]) + kc1[k]] = ta[k];
        d_csr_g1[__ldg(&d_off_g1[ta[k]]) + kg1[k]] = sa[k];
        d_csr_c2[__ldg(&d_off_c2[sc[k]]) + kc2[k]] = tc[k];
        d_csr_g2[__ldg(&d_off_g2[tc[k]]) + kg2[k]] = sc[k];
    }
}

// init: accumulators + pre-scaled layer-0 feature tables
__global__ void scale_init_kernel(const float4* __restrict__ cf1,
                                  const float4* __restrict__ cf2,
                                  const float4* __restrict__ gf) {
    int i = blockIdx.x * blockDim.x + threadIdx.x;
    if (i < NC*16) {
        int row = i >> 4;
        float4 x1 = __ldg(&cf1[i]), x2 = __ldg(&cf2[i]);
        float w1 = __ldg(&d_cj1[row]), w2 = __ldg(&d_cj2[row]);
        ((float4*)d_u1)[i]  = make_float4(W3*x1.x, W3*x1.y, W3*x1.z, W3*x1.w);
        ((float4*)d_u2)[i]  = make_float4(W3*x2.x, W3*x2.y, W3*x2.z, W3*x2.w);
        ((float4*)d_s1a)[i] = make_float4(w1*x1.x, w1*x1.y, w1*x1.z, w1*x1.w);
        ((float4*)d_s2a)[i] = make_float4(w2*x2.x, w2*x2.y, w2*x2.z, w2*x2.w);
    }
    if (i < NG*16) {
        int row = i >> 4;
        float4 g = __ldg(&gf[i]);
        float w1 = __ldg(&d_ci1[row]), w2 = __ldg(&d_ci2[row]);
        ((float4*)d_ih)[i]   = make_float4(W3*g.x, W3*g.y, W3*g.z, W3*g.w);
        ((float4*)d_sg1a)[i] = make_float4(w1*g.x, w1*g.y, w1*g.z, w1*g.w);
        ((float4*)d_sg2a)[i] = make_float4(w2*g.x, w2*g.y, w2*g.z, w2*g.w);
    }
}

// ---------------- SpMM: warp-centric gather over pre-scaled rows -----------
// block = 128 threads per gene: warps {0,1}->rel1 halves, {2,3}->rel2 halves
__global__ void gene_spmm_kernel(int layer) {
    const float2* C1 = (const float2*)(layer ? d_s1b : d_s1a);
    const float2* C2 = (const float2*)(layer ? d_s2b : d_s2a);
    const int g    = blockIdx.x;
    const int w    = threadIdx.x >> 5;
    const int lane = threadIdx.x & 31;
    const int rel  = w >> 1;
    const int half = w & 1;

    const int*    csr = rel ? d_csr_g2 : d_csr_g1;
    const float2* C   = rel ? C2       : C1;
    const int beg = rel ? d_off_g2[g]  : d_off_g1[g];
    const int cnt = rel ? d_deg_dst2[g]: d_deg_dst1[g];

    float2 acc = make_float2(0.f, 0.f);
    for (int base = half * 32; base < cnt; base += 64) {
        int p = base + lane;
        int idx = (p < cnt) ? __ldg(&csr[beg + p]) : NC;  // NC = zero dummy row
        #pragma unroll
        for (int j = 0; j < 32; j++) {
            int bi = __shfl_sync(0xffffffffu, idx, j);
            float2 v = __ldg(&C[bi * 32 + lane]);
            acc.x += v.x; acc.y += v.y;
        }
    }
    __shared__ float2 part[4][32];
    part[w][lane] = acc;
    __syncthreads();
    if (threadIdx.x < 32) {
        float2 a0 = part[0][lane], a1 = part[1][lane];
        float2 a2 = part[2][lane], a3 = part[3][lane];
        float c1s = d_ci1[g], c2s = d_ci2[g];
        float2 go;
        go.x = 0.5f * (c1s * (a0.x + a1.x) + c2s * (a2.x + a3.x));
        go.y = 0.5f * (c1s * (a0.y + a1.y) + c2s * (a2.y + a3.y));
        float2 ih = ((float2*)d_ih)[g * 32 + lane];
        ih.x += W3 * go.x; ih.y += W3 * go.y;
        ((float2*)d_ih)[g * 32 + lane] = ih;
        if (!layer) {
            ((float2*)d_sg1b)[g * 32 + lane] = make_float2(c1s * go.x, c1s * go.y);
            ((float2*)d_sg2b)[g * 32 + lane] = make_float2(c2s * go.x, c2s * go.y);
        }
    }
}

// block = 256 threads = 4 cells x 2 relations; warps fully independent
__global__ void cell_spmm_kernel(int layer) {
    const float2* G1 = (const float2*)(layer ? d_sg1b : d_sg1a);
    const float2* G2 = (const float2*)(layer ? d_sg2b : d_sg2a);
    const int c    = blockIdx.x * 4 + (threadIdx.x >> 6);
    const int rel  = (threadIdx.x >> 5) & 1;
    const int lane = threadIdx.x & 31;
    if (c >= NC) return;

    const int*    csr = rel ? d_csr_c2 : d_csr_c1;
    const float2* G   = rel ? G2       : G1;
    const int beg = rel ? d_off_c2[c]  : d_off_c1[c];
    const int cnt = rel ? d_deg_src2[c]: d_deg_src1[c];

    float2 acc = make_float2(0.f, 0.f);
    for (int base = 0; base < cnt; base += 32) {
        int p = base + lane;
        int idx = (p < cnt) ? __ldg(&csr[beg + p]) : NG;  // NG = zero dummy row
        #pragma unroll
        for (int j = 0; j < 32; j++) {
            int bi = __shfl_sync(0xffffffffu, idx, j);
            float2 v = __ldg(&G[bi * 32 + lane]);
            acc.x += v.x; acc.y += v.y;
        }
    }
    float s = rel ? d_cj2[c] : d_cj1[c];
    float vx = s * acc.x, vy = s * acc.y;
    float2* u = rel ? (float2*)d_u2 : (float2*)d_u1;
    float2 uv = u[c * 32 + lane];
    uv.x += W3 * vx; uv.y += W3 * vy;
    u[c * 32 + lane] = uv;
    if (!layer) {  // layer-2 gene gather input: cj * new cell features
        float2* t = rel ? (float2*)d_s2b : (float2*)d_s1b;
        t[c * 32 + lane] = make_float2(s * vx, s * vy);
    }
}

// ---------------- embed: y = ELU(BN(u @ W[:64] + b + W[64+branch])) --------
__global__ void emb_kernel(const float* __restrict__ Wm, const float* __restrict__ bb,
                           const float* __restrict__ gam, const float* __restrict__ bet,
                           const float* __restrict__ mu,  const float* __restrict__ var) {
    const int branch = blockIdx.y;
    const float* __restrict__ U  = branch ? d_u2  : d_u1;
    float* __restrict__ UF       = branch ? d_uf2 : d_uf1;

    __shared__ float sU[64][65];
    __shared__ float sW[64][64];
    int tid = threadIdx.x;
    int row0 = blockIdx.x * 64;

    for (int t = tid; t < 64*64; t += 256) sW[t/64][t%64] = Wm[t];
    for (int t = tid; t < 64*64; t += 256) {
        int r = t / 64, k = t % 64;
        int gr = row0 + r;
        sU[r][k] = (gr < NC) ? U[gr*D + k] : 0.f;
    }
    __syncthreads();

    int c  = tid & 63;
    int rq = tid >> 6;
    float acc[16];
    #pragma unroll
    for (int rr = 0; rr < 16; rr++) acc[rr] = 0.f;
    #pragma unroll 8
    for (int k = 0; k < 64; k++) {
        float w = sW[k][c];
        #pragma unroll
        for (int rr = 0; rr < 16; rr++)
            acc[rr] = fmaf(sU[rq*16 + rr][k], w, acc[rr]);
    }
    float scale = gam[c] * rsqrtf(var[c] + BN_EPS);
    float shift = bet[c] - mu[c] * scale;
    float beff  = bb[c] + Wm[(64 + branch)*64 + c];
    #pragma unroll
    for (int rr = 0; rr < 16; rr++) {
        int r = row0 + rq*16 + rr;
        if (r < NC) {
            float y = (acc[rr] + beff) * scale + shift;
            UF[r*D + c] = y > 0.f ? y : expm1f(y);
        }
    }
}

// ---------------- decoder: 16 lanes per edge, float4 ----------------------
__global__ void dot_kernel(const int* __restrict__ ps1, const int* __restrict__ pd1,
                           const int* __restrict__ ps2, const int* __restrict__ pd2,
                           float* __restrict__ out) {
    int t = blockIdx.x * blockDim.x + threadIdx.x;
    int e = t >> 4;
    int l = t & 15;
    if (e >= 2*NP) return;
    const float4* uf; int s, d;
    if (e < NP) { uf = (const float4*)d_uf1; s = __ldg(&ps1[e]); d = __ldg(&pd1[e]); }
    else { int e2 = e - NP; uf = (const float4*)d_uf2; s = __ldg(&ps2[e2]); d = __ldg(&pd2[e2]); }
    float4 a = __ldg(&uf[s * 16 + l]);
    float4 b = __ldg(&((const float4*)d_ih)[d * 16 + l]);
    float v = a.x*b.x + a.y*b.y + a.z*b.z + a.w*b.w;
    v += __shfl_xor_sync(0xffffffffu, v, 8);
    v += __shfl_xor_sync(0xffffffffu, v, 4);
    v += __shfl_xor_sync(0xffffffffu, v, 2);
    v += __shfl_xor_sync(0xffffffffu, v, 1);
    if (l == 0) out[e] = v;
}

// ---------------- host ------------------------------------------------------
extern "C" void kernel_launch(void* const* d_in, const int* in_sizes, int n_in,
                              void* d_out, int out_size) {
    const float* cf1 = (const float*)d_in[0];
    const float* cf2 = (const float*)d_in[1];
    const float* gf  = (const float*)d_in[2];
    const float* Wm  = (const float*)d_in[3];
    const float* bb  = (const float*)d_in[4];
    const float* gam = (const float*)d_in[5];
    const float* bet = (const float*)d_in[6];
    const float* mu  = (const float*)d_in[7];
    const float* var = (const float*)d_in[8];
    const int* es1 = (const int*)d_in[9];
    const int* ed1 = (const int*)d_in[10];
    const int* es2 = (const int*)d_in[11];
    const int* ed2 = (const int*)d_in[12];
    const int* ps1 = (const int*)d_in[13];
    const int* pd1 = (const int*)d_in[14];
    const int* ps2 = (const int*)d_in[15];
    const int* pd2 = (const int*)d_in[16];
    float* out = (float*)d_out;

    zero_kernel   <<<(NC + 255)/256, 256>>>();
    hist_kernel   <<<(NE/4 + 255)/256, 256>>>((const int4*)es1, (const int4*)ed1,
                                              (const int4*)es2, (const int4*)ed2);
    prep_kernel   <<<(NC + 255)/256, 256>>>();
    scatter_kernel<<<(NE/4 + 255)/256, 256>>>((const int4*)es1, (const int4*)ed1,
                                              (const int4*)es2, (const int4*)ed2);
    scale_init_kernel<<<(NC*16 + 255)/256, 256>>>((const float4*)cf1, (const float4*)cf2,
                                                  (const float4*)gf);

    // layer 1
    gene_spmm_kernel<<<NG, 128>>>(0);
    cell_spmm_kernel<<<(NC + 3)/4, 256>>>(0);
    // layer 2
    gene_spmm_kernel<<<NG, 128>>>(1);
    cell_spmm_kernel<<<(NC + 3)/4, 256>>>(1);

    emb_kernel<<<dim3((NC + 63)/64, 2), 256>>>(Wm, bb, gam, bet, mu, var);
    dot_kernel<<<(2*NP*16 + 255)/256, 256>>>(ps1, pd1, ps2, pd2, out);
}

// round 5
// speedup vs baseline: 1.6260x; 1.0522x over previous
#include <cuda_runtime.h>
#include <cuda_fp16.h>
#include <math.h>

#define NC 50000
#define NG 2000
#define D  64
#define NE 1000000
#define NP 500000
#define W3 (1.0f/3.0f)
#define BN_EPS 1e-5f

#define NGB (NG/2)          // gene blocks in fused layer kernel (2 genes/block)
#define NCB ((NC+3)/4)      // cell blocks (4 cells/block)

// ---------------- scratch (static device globals) --------------------------
__device__ int   d_deg_src1[NC], d_deg_src2[NC];
__device__ int   d_deg_dst1[NG], d_deg_dst2[NG];
__device__ int   d_off_c1[NC], d_off_c2[NC];
__device__ int   d_off_g1[NG], d_off_g2[NG];
__device__ float d_cj1[NC], d_cj2[NC], d_ci1[NG], d_ci2[NG];
__device__ int   d_ctr[4];
__device__ int   d_rk_c1[NE], d_rk_c2[NE], d_rk_g1[NE], d_rk_g2[NE];
__device__ int   d_csr_g1[NE], d_csr_g2[NE];   // cell ids grouped by gene
__device__ int   d_csr_c1[NE], d_csr_c2[NE];   // gene ids grouped by cell
// pre-scaled fp16 feature tables (+1 zero dummy row each)
__device__ __half d_s1a[(NC+1)*D], d_s2a[(NC+1)*D];   // cj * cell feats, layer in
__device__ __half d_s1b[(NC+1)*D], d_s2b[(NC+1)*D];   // cj * cell feats, layer1 out
__device__ __half d_sg1a[(NG+1)*D], d_sg2a[(NG+1)*D]; // ci * gene feats, layer in
__device__ __half d_sg1b[(NG+1)*D], d_sg2b[(NG+1)*D]; // ci * gene feats, layer1 out
__device__ float d_ih[NG*D];
__device__ float d_u1[NC*D],  d_u2[NC*D];
__device__ float d_uf1[NC*D], d_uf2[NC*D];

// ---------------- setup -----------------------------------------------------
__global__ void zero_kernel() {
    int i = blockIdx.x * blockDim.x + threadIdx.x;
    if (i < NC) { d_deg_src1[i]=0; d_deg_src2[i]=0; }
    if (i < NG) { d_deg_dst1[i]=0; d_deg_dst2[i]=0; }
    if (i < 4)  d_ctr[i] = 0;
    if (i < 8) {  // zero dummy rows: 64 halves = 8 float4 per table
        float4 z = make_float4(0,0,0,0);
        ((float4*)(d_s1a  + NC*D))[i] = z;
        ((float4*)(d_s2a  + NC*D))[i] = z;
        ((float4*)(d_s1b  + NC*D))[i] = z;
        ((float4*)(d_s2b  + NC*D))[i] = z;
        ((float4*)(d_sg1a + NG*D))[i] = z;
        ((float4*)(d_sg2a + NG*D))[i] = z;
        ((float4*)(d_sg1b + NG*D))[i] = z;
        ((float4*)(d_sg2b + NG*D))[i] = z;
    }
}

// single atomic pass: counters + per-edge ranks (rank stores coalesced int4)
__global__ void hist_kernel(const int4* __restrict__ s1, const int4* __restrict__ t1,
                            const int4* __restrict__ s2, const int4* __restrict__ t2) {
    int i = blockIdx.x * blockDim.x + threadIdx.x;
    if (i >= NE/4) return;
    int4 a = __ldg(&s1[i]), b = __ldg(&t1[i]);
    int4 c = __ldg(&s2[i]), e = __ldg(&t2[i]);
    int4 r;
    r.x = atomicAdd(&d_deg_src1[a.x],1); r.y = atomicAdd(&d_deg_src1[a.y],1);
    r.z = atomicAdd(&d_deg_src1[a.z],1); r.w = atomicAdd(&d_deg_src1[a.w],1);
    ((int4*)d_rk_c1)[i] = r;
    r.x = atomicAdd(&d_deg_dst1[b.x],1); r.y = atomicAdd(&d_deg_dst1[b.y],1);
    r.z = atomicAdd(&d_deg_dst1[b.z],1); r.w = atomicAdd(&d_deg_dst1[b.w],1);
    ((int4*)d_rk_g1)[i] = r;
    r.x = atomicAdd(&d_deg_src2[c.x],1); r.y = atomicAdd(&d_deg_src2[c.y],1);
    r.z = atomicAdd(&d_deg_src2[c.z],1); r.w = atomicAdd(&d_deg_src2[c.w],1);
    ((int4*)d_rk_c2)[i] = r;
    r.x = atomicAdd(&d_deg_dst2[e.x],1); r.y = atomicAdd(&d_deg_dst2[e.y],1);
    r.z = atomicAdd(&d_deg_dst2[e.z],1); r.w = atomicAdd(&d_deg_dst2[e.w],1);
    ((int4*)d_rk_g2)[i] = r;
}

__device__ __forceinline__ int warp_alloc(int v, int* ctr, int lane) {
    int x = v;
    #pragma unroll
    for (int d = 1; d < 32; d <<= 1) {
        int y = __shfl_up_sync(0xffffffffu, x, d);
        if (lane >= d) x += y;
    }
    int tot = __shfl_sync(0xffffffffu, x, 31);
    int base = 0;
    if (lane == 31) base = atomicAdd(ctr, tot);
    base = __shfl_sync(0xffffffffu, base, 31);
    return base + x - v;
}

__global__ void prep_kernel() {
    int i = blockIdx.x * blockDim.x + threadIdx.x;
    int lane = threadIdx.x & 31;
    int dg1 = (i < NC) ? d_deg_src1[i] : 0;
    int dg2 = (i < NC) ? d_deg_src2[i] : 0;
    int o1 = warp_alloc(dg1, &d_ctr[0], lane);
    int o2 = warp_alloc(dg2, &d_ctr[1], lane);
    if (i < NC) {
        d_cj1[i] = dg1 ? rsqrtf((float)dg1) : 0.f;
        d_cj2[i] = dg2 ? rsqrtf((float)dg2) : 0.f;
        d_off_c1[i] = o1;
        d_off_c2[i] = o2;
    }
    if (i - lane < NG) {
        int e1 = (i < NG) ? d_deg_dst1[i] : 0;
        int e2 = (i < NG) ? d_deg_dst2[i] : 0;
        int p1 = warp_alloc(e1, &d_ctr[2], lane);
        int p2 = warp_alloc(e2, &d_ctr[3], lane);
        if (i < NG) {
            d_ci1[i] = e1 ? rsqrtf((float)e1) : 0.f;
            d_ci2[i] = e2 ? rsqrtf((float)e2) : 0.f;
            d_off_g1[i] = p1;
            d_off_g2[i] = p2;
        }
    }
}

// atomic-free scatter: slot = off[node] + precomputed rank
__global__ void scatter_kernel(const int4* __restrict__ s1, const int4* __restrict__ t1,
                               const int4* __restrict__ s2, const int4* __restrict__ t2) {
    int i = blockIdx.x * blockDim.x + threadIdx.x;
    if (i >= NE/4) return;
    int4 a = __ldg(&s1[i]), b = __ldg(&t1[i]);
    int4 c = __ldg(&s2[i]), e = __ldg(&t2[i]);
    int4 rc1 = __ldg(&((const int4*)d_rk_c1)[i]);
    int4 rg1 = __ldg(&((const int4*)d_rk_g1)[i]);
    int4 rc2 = __ldg(&((const int4*)d_rk_c2)[i]);
    int4 rg2 = __ldg(&((const int4*)d_rk_g2)[i]);
    int sa[4] = {a.x,a.y,a.z,a.w}, ta[4] = {b.x,b.y,b.z,b.w};
    int sc[4] = {c.x,c.y,c.z,c.w}, tc[4] = {e.x,e.y,e.z,e.w};
    int kc1[4] = {rc1.x,rc1.y,rc1.z,rc1.w}, kg1[4] = {rg1.x,rg1.y,rg1.z,rg1.w};
    int kc2[4] = {rc2.x,rc2.y,rc2.z,rc2.w}, kg2[4] = {rg2.x,rg2.y,rg2.z,rg2.w};
    #pragma unroll
    for (int k = 0; k < 4; k++) {
        d_csr_c1[__ldg(&d_off_c1[sa[k]]) + kc1[k]] = ta[k];
        d_csr_g1[__ldg(&d_off_g1[ta[k]]) + kg1[k]] = sa[k];
        d_csr_c2[__ldg(&d_off_c2[sc[k]]) + kc2[k]] = tc[k];
        d_csr_g2[__ldg(&d_off_g2[tc[k]]) + kg2[k]] = sc[k];
    }
}

// init: fp32 accumulators + pre-scaled fp16 layer-0 tables
__global__ void scale_init_kernel(const float4* __restrict__ cf1,
                                  const float4* __restrict__ cf2,
                                  const float4* __restrict__ gf) {
    int i = blockIdx.x * blockDim.x + threadIdx.x;
    if (i < NC*16) {
        int row = i >> 4;
        float4 x1 = __ldg(&cf1[i]), x2 = __ldg(&cf2[i]);
        float w1 = __ldg(&d_cj1[row]), w2 = __ldg(&d_cj2[row]);
        ((float4*)d_u1)[i] = make_float4(W3*x1.x, W3*x1.y, W3*x1.z, W3*x1.w);
        ((float4*)d_u2)[i] = make_float4(W3*x2.x, W3*x2.y, W3*x2.z, W3*x2.w);
        ((__half2*)d_s1a)[2*i]   = __floats2half2_rn(w1*x1.x, w1*x1.y);
        ((__half2*)d_s1a)[2*i+1] = __floats2half2_rn(w1*x1.z, w1*x1.w);
        ((__half2*)d_s2a)[2*i]   = __floats2half2_rn(w2*x2.x, w2*x2.y);
        ((__half2*)d_s2a)[2*i+1] = __floats2half2_rn(w2*x2.z, w2*x2.w);
    }
    if (i < NG*16) {
        int row = i >> 4;
        float4 g = __ldg(&gf[i]);
        float w1 = __ldg(&d_ci1[row]), w2 = __ldg(&d_ci2[row]);
        ((float4*)d_ih)[i] = make_float4(W3*g.x, W3*g.y, W3*g.z, W3*g.w);
        ((__half2*)d_sg1a)[2*i]   = __floats2half2_rn(w1*g.x, w1*g.y);
        ((__half2*)d_sg1a)[2*i+1] = __floats2half2_rn(w1*g.z, w1*g.w);
        ((__half2*)d_sg2a)[2*i]   = __floats2half2_rn(w2*g.x, w2*g.y);
        ((__half2*)d_sg2a)[2*i+1] = __floats2half2_rn(w2*g.z, w2*g.w);
    }
}

// warp gather helper: indices batched 32-wide, rows consumed in unroll-8 chunks
__device__ __forceinline__ void gather_rows(const __half2* __restrict__ C,
                                            const int* __restrict__ csr,
                                            int beg, int cnt, int start, int step,
                                            int dummy, int lane, float2& acc) {
    for (int base = start; base < cnt; base += step) {
        int p = base + lane;
        int idx = (p < cnt) ? __ldg(&csr[beg + p]) : dummy;
        int m = min(32, cnt - base);
        for (int j0 = 0; j0 < m; j0 += 8) {
            #pragma unroll
            for (int jj = 0; jj < 8; jj++) {
                int bi = __shfl_sync(0xffffffffu, idx, j0 + jj);
                float2 v = __half22float2(__ldg(&C[bi * 32 + lane]));
                acc.x += v.x; acc.y += v.y;
            }
        }
    }
}

// ---------------- fused per-layer SpMM --------------------------------------
// grid = NGB + NCB, 256 threads.
// blocks [0, NGB): 2 genes each (4 warps/gene: 2 rel x 2 halves)
// blocks [NGB, ..): 4 cells each (2 warps/cell: 1 per rel)
__global__ void layer_kernel(int layer) {
    const int tid  = threadIdx.x;
    const int lane = tid & 31;

    if (blockIdx.x < NGB) {
        const __half2* C1 = (const __half2*)(layer ? d_s1b : d_s1a);
        const __half2* C2 = (const __half2*)(layer ? d_s2b : d_s2a);
        const int gl   = tid >> 7;            // gene within block
        const int g    = blockIdx.x * 2 + gl;
        const int lw   = (tid >> 5) & 3;      // warp within gene
        const int rel  = lw >> 1;
        const int half = lw & 1;

        const int*     csr = rel ? d_csr_g2 : d_csr_g1;
        const __half2* C   = rel ? C2       : C1;
        const int beg = rel ? d_off_g2[g]  : d_off_g1[g];
        const int cnt = rel ? d_deg_dst2[g]: d_deg_dst1[g];

        float2 acc = make_float2(0.f, 0.f);
        gather_rows(C, csr, beg, cnt, half * 32, 64, NC, lane, acc);

        __shared__ float2 part[8][32];
        part[tid >> 5][lane] = acc;
        __syncthreads();
        if ((tid & 127) < 32) {
            float2 a0 = part[gl*4+0][lane], a1 = part[gl*4+1][lane];
            float2 a2 = part[gl*4+2][lane], a3 = part[gl*4+3][lane];
            float c1s = d_ci1[g], c2s = d_ci2[g];
            float2 go;
            go.x = 0.5f * (c1s * (a0.x + a1.x) + c2s * (a2.x + a3.x));
            go.y = 0.5f * (c1s * (a0.y + a1.y) + c2s * (a2.y + a3.y));
            float2 ih = ((float2*)d_ih)[g * 32 + lane];
            ih.x += W3 * go.x; ih.y += W3 * go.y;
            ((float2*)d_ih)[g * 32 + lane] = ih;
            if (!layer) {
                ((__half2*)d_sg1b)[g * 32 + lane] = __floats2half2_rn(c1s*go.x, c1s*go.y);
                ((__half2*)d_sg2b)[g * 32 + lane] = __floats2half2_rn(c2s*go.x, c2s*go.y);
            }
        }
    } else {
        const __half2* G1 = (const __half2*)(layer ? d_sg1b : d_sg1a);
        const __half2* G2 = (const __half2*)(layer ? d_sg2b : d_sg2a);
        const int c   = (blockIdx.x - NGB) * 4 + (tid >> 6);
        const int rel = (tid >> 5) & 1;
        if (c >= NC) return;

        const int*     csr = rel ? d_csr_c2 : d_csr_c1;
        const __half2* G   = rel ? G2       : G1;
        const int beg = rel ? d_off_c2[c]  : d_off_c1[c];
        const int cnt = rel ? d_deg_src2[c]: d_deg_src1[c];

        float2 acc = make_float2(0.f, 0.f);
        gather_rows(G, csr, beg, cnt, 0, 32, NG, lane, acc);

        float s = rel ? d_cj2[c] : d_cj1[c];
        float vx = s * acc.x, vy = s * acc.y;
        float2* u = rel ? (float2*)d_u2 : (float2*)d_u1;
        float2 uv = u[c * 32 + lane];
        uv.x += W3 * vx; uv.y += W3 * vy;
        u[c * 32 + lane] = uv;
        if (!layer) {  // next-layer gene gather input: cj * new cell features
            __half2* t = rel ? (__half2*)d_s2b : (__half2*)d_s1b;
            t[c * 32 + lane] = __floats2half2_rn(s * vx, s * vy);
        }
    }
}

// ---------------- embed: y = ELU(BN(u @ W[:64] + b + W[64+branch])) --------
__global__ void emb_kernel(const float* __restrict__ Wm, const float* __restrict__ bb,
                           const float* __restrict__ gam, const float* __restrict__ bet,
                           const float* __restrict__ mu,  const float* __restrict__ var) {
    const int branch = blockIdx.y;
    const float* __restrict__ U  = branch ? d_u2  : d_u1;
    float* __restrict__ UF       = branch ? d_uf2 : d_uf1;

    __shared__ float sU[64][65];
    __shared__ float sW[64][64];
    int tid = threadIdx.x;
    int row0 = blockIdx.x * 64;

    for (int t = tid; t < 64*64; t += 256) sW[t/64][t%64] = Wm[t];
    for (int t = tid; t < 64*64; t += 256) {
        int r = t / 64, k = t % 64;
        int gr = row0 + r;
        sU[r][k] = (gr < NC) ? U[gr*D + k] : 0.f;
    }
    __syncthreads();

    int c  = tid & 63;
    int rq = tid >> 6;
    float acc[16];
    #pragma unroll
    for (int rr = 0; rr < 16; rr++) acc[rr] = 0.f;
    #pragma unroll 8
    for (int k = 0; k < 64; k++) {
        float w = sW[k][c];
        #pragma unroll
        for (int rr = 0; rr < 16; rr++)
            acc[rr] = fmaf(sU[rq*16 + rr][k], w, acc[rr]);
    }
    float scale = gam[c] * rsqrtf(var[c] + BN_EPS);
    float shift = bet[c] - mu[c] * scale;
    float beff  = bb[c] + Wm[(64 + branch)*64 + c];
    #pragma unroll
    for (int rr = 0; rr < 16; rr++) {
        int r = row0 + rq*16 + rr;
        if (r < NC) {
            float y = (acc[rr] + beff) * scale + shift;
            UF[r*D + c] = y > 0.f ? y : expm1f(y);
        }
    }
}

// ---------------- decoder: 16 lanes per edge, float4 -----------------------
__global__ void dot_kernel(const int* __restrict__ ps1, const int* __restrict__ pd1,
                           const int* __restrict__ ps2, const int* __restrict__ pd2,
                           float* __restrict__ out) {
    int t = blockIdx.x * blockDim.x + threadIdx.x;
    int e = t >> 4;
    int l = t & 15;
    if (e >= 2*NP) return;
    const float4* uf; int s, d;
    if (e < NP) { uf = (const float4*)d_uf1; s = __ldg(&ps1[e]); d = __ldg(&pd1[e]); }
    else { int e2 = e - NP; uf = (const float4*)d_uf2; s = __ldg(&ps2[e2]); d = __ldg(&pd2[e2]); }
    float4 a = __ldg(&uf[s * 16 + l]);
    float4 b = __ldg(&((const float4*)d_ih)[d * 16 + l]);
    float v = a.x*b.x + a.y*b.y + a.z*b.z + a.w*b.w;
    v += __shfl_xor_sync(0xffffffffu, v, 8);
    v += __shfl_xor_sync(0xffffffffu, v, 4);
    v += __shfl_xor_sync(0xffffffffu, v, 2);
    v += __shfl_xor_sync(0xffffffffu, v, 1);
    if (l == 0) out[e] = v;
}

// ---------------- host ------------------------------------------------------
extern "C" void kernel_launch(void* const* d_in, const int* in_sizes, int n_in,
                              void* d_out, int out_size) {
    const float* cf1 = (const float*)d_in[0];
    const float* cf2 = (const float*)d_in[1];
    const float* gf  = (const float*)d_in[2];
    const float* Wm  = (const float*)d_in[3];
    const float* bb  = (const float*)d_in[4];
    const float* gam = (const float*)d_in[5];
    const float* bet = (const float*)d_in[6];
    const float* mu  = (const float*)d_in[7];
    const float* var = (const float*)d_in[8];
    const int* es1 = (const int*)d_in[9];
    const int* ed1 = (const int*)d_in[10];
    const int* es2 = (const int*)d_in[11];
    const int* ed2 = (const int*)d_in[12];
    const int* ps1 = (const int*)d_in[13];
    const int* pd1 = (const int*)d_in[14];
    const int* ps2 = (const int*)d_in[15];
    const int* pd2 = (const int*)d_in[16];
    float* out = (float*)d_out;

    zero_kernel   <<<(NC + 255)/256, 256>>>();
    hist_kernel   <<<(NE/4 + 255)/256, 256>>>((const int4*)es1, (const int4*)ed1,
                                              (const int4*)es2, (const int4*)ed2);
    prep_kernel   <<<(NC + 255)/256, 256>>>();
    scatter_kernel<<<(NE/4 + 255)/256, 256>>>((const int4*)es1, (const int4*)ed1,
                                              (const int4*)es2, (const int4*)ed2);
    scale_init_kernel<<<(NC*16 + 255)/256, 256>>>((const float4*)cf1, (const float4*)cf2,
                                                  (const float4*)gf);

    layer_kernel<<<NGB + NCB, 256>>>(0);
    layer_kernel<<<NGB + NCB, 256>>>(1);

    emb_kernel<<<dim3((NC + 63)/64, 2), 256>>>(Wm, bb, gam, bet, mu, var);
    dot_kernel<<<(2*NP*16 + 255)/256, 256>>>(ps1, pd1, ps2, pd2, out);
}

// round 6
// speedup vs baseline: 1.7333x; 1.0660x over previous
#include <cuda_runtime.h>
#include <cuda_fp16.h>
#include <math.h>

#define NC 50000
#define NG 2000
#define D  64
#define NE 1000000
#define NP 500000
#define W3 (1.0f/3.0f)
#define BN_EPS 1e-5f

#define NGB (NG/2)          // gene blocks (2 genes/block)
#define NCB ((NC+3)/4)      // cell blocks (4 cells/block)

// ---------------- scratch (static device globals) --------------------------
__device__ int   d_deg_src1[NC], d_deg_src2[NC];
__device__ int   d_deg_dst1[NG], d_deg_dst2[NG];
__device__ int   d_off_c1[NC], d_off_c2[NC];
__device__ int   d_off_g1[NG], d_off_g2[NG];
__device__ float d_cj1[NC], d_cj2[NC], d_ci1[NG], d_ci2[NG];
__device__ int   d_ctr[4];
__device__ int   d_rk_c1[NE], d_rk_c2[NE], d_rk_g1[NE], d_rk_g2[NE];
__device__ int   d_csr_g1[NE], d_csr_g2[NE];   // cell ids grouped by gene
__device__ int   d_csr_c1[NE], d_csr_c2[NE];   // gene ids grouped by cell
// pre-scaled fp16 tables, 8 x uint4 per row (64 halves); +1 zero dummy row
__device__ uint4 d_s1a[(NC+1)*8], d_s2a[(NC+1)*8];   // cj * cell feats, layer in
__device__ uint4 d_s1b[(NC+1)*8], d_s2b[(NC+1)*8];   // cj * cell feats, layer1 out
__device__ uint4 d_sg1a[(NG+1)*8], d_sg2a[(NG+1)*8]; // ci * gene feats, layer in
__device__ uint4 d_sg1b[(NG+1)*8], d_sg2b[(NG+1)*8]; // ci * gene feats, layer1 out
__device__ float d_ih[NG*D];
__device__ float d_u1[NC*D],  d_u2[NC*D];
// fp16 decoder tables
__device__ uint4 d_ufh1[NC*8], d_ufh2[NC*8], d_ihh[NG*8];

// ---------------- setup -----------------------------------------------------
__global__ void zero_kernel() {
    int i = blockIdx.x * blockDim.x + threadIdx.x;
    if (i < NC) { d_deg_src1[i]=0; d_deg_src2[i]=0; }
    if (i < NG) { d_deg_dst1[i]=0; d_deg_dst2[i]=0; }
    if (i < 4)  d_ctr[i] = 0;
    if (i < 8) {  // zero dummy rows (8 uint4 each)
        uint4 z = make_uint4(0,0,0,0);
        d_s1a [NC*8 + i] = z; d_s2a [NC*8 + i] = z;
        d_s1b [NC*8 + i] = z; d_s2b [NC*8 + i] = z;
        d_sg1a[NG*8 + i] = z; d_sg2a[NG*8 + i] = z;
        d_sg1b[NG*8 + i] = z; d_sg2b[NG*8 + i] = z;
    }
}

// single atomic pass: counters + per-edge ranks (rank stores coalesced int4)
__global__ void hist_kernel(const int4* __restrict__ s1, const int4* __restrict__ t1,
                            const int4* __restrict__ s2, const int4* __restrict__ t2) {
    int i = blockIdx.x * blockDim.x + threadIdx.x;
    if (i >= NE/4) return;
    int4 a = __ldg(&s1[i]), b = __ldg(&t1[i]);
    int4 c = __ldg(&s2[i]), e = __ldg(&t2[i]);
    int4 r;
    r.x = atomicAdd(&d_deg_src1[a.x],1); r.y = atomicAdd(&d_deg_src1[a.y],1);
    r.z = atomicAdd(&d_deg_src1[a.z],1); r.w = atomicAdd(&d_deg_src1[a.w],1);
    ((int4*)d_rk_c1)[i] = r;
    r.x = atomicAdd(&d_deg_dst1[b.x],1); r.y = atomicAdd(&d_deg_dst1[b.y],1);
    r.z = atomicAdd(&d_deg_dst1[b.z],1); r.w = atomicAdd(&d_deg_dst1[b.w],1);
    ((int4*)d_rk_g1)[i] = r;
    r.x = atomicAdd(&d_deg_src2[c.x],1); r.y = atomicAdd(&d_deg_src2[c.y],1);
    r.z = atomicAdd(&d_deg_src2[c.z],1); r.w = atomicAdd(&d_deg_src2[c.w],1);
    ((int4*)d_rk_c2)[i] = r;
    r.x = atomicAdd(&d_deg_dst2[e.x],1); r.y = atomicAdd(&d_deg_dst2[e.y],1);
    r.z = atomicAdd(&d_deg_dst2[e.z],1); r.w = atomicAdd(&d_deg_dst2[e.w],1);
    ((int4*)d_rk_g2)[i] = r;
}

__device__ __forceinline__ int warp_alloc(int v, int* ctr, int lane) {
    int x = v;
    #pragma unroll
    for (int d = 1; d < 32; d <<= 1) {
        int y = __shfl_up_sync(0xffffffffu, x, d);
        if (lane >= d) x += y;
    }
    int tot = __shfl_sync(0xffffffffu, x, 31);
    int base = 0;
    if (lane == 31) base = atomicAdd(ctr, tot);
    base = __shfl_sync(0xffffffffu, base, 31);
    return base + x - v;
}

__global__ void prep_kernel() {
    int i = blockIdx.x * blockDim.x + threadIdx.x;
    int lane = threadIdx.x & 31;
    int dg1 = (i < NC) ? d_deg_src1[i] : 0;
    int dg2 = (i < NC) ? d_deg_src2[i] : 0;
    int o1 = warp_alloc(dg1, &d_ctr[0], lane);
    int o2 = warp_alloc(dg2, &d_ctr[1], lane);
    if (i < NC) {
        d_cj1[i] = dg1 ? rsqrtf((float)dg1) : 0.f;
        d_cj2[i] = dg2 ? rsqrtf((float)dg2) : 0.f;
        d_off_c1[i] = o1;
        d_off_c2[i] = o2;
    }
    if (i - lane < NG) {
        int e1 = (i < NG) ? d_deg_dst1[i] : 0;
        int e2 = (i < NG) ? d_deg_dst2[i] : 0;
        int p1 = warp_alloc(e1, &d_ctr[2], lane);
        int p2 = warp_alloc(e2, &d_ctr[3], lane);
        if (i < NG) {
            d_ci1[i] = e1 ? rsqrtf((float)e1) : 0.f;
            d_ci2[i] = e2 ? rsqrtf((float)e2) : 0.f;
            d_off_g1[i] = p1;
            d_off_g2[i] = p2;
        }
    }
}

// atomic-free scatter: slot = off[node] + precomputed rank
__global__ void scatter_kernel(const int4* __restrict__ s1, const int4* __restrict__ t1,
                               const int4* __restrict__ s2, const int4* __restrict__ t2) {
    int i = blockIdx.x * blockDim.x + threadIdx.x;
    if (i >= NE/4) return;
    int4 a = __ldg(&s1[i]), b = __ldg(&t1[i]);
    int4 c = __ldg(&s2[i]), e = __ldg(&t2[i]);
    int4 rc1 = __ldg(&((const int4*)d_rk_c1)[i]);
    int4 rg1 = __ldg(&((const int4*)d_rk_g1)[i]);
    int4 rc2 = __ldg(&((const int4*)d_rk_c2)[i]);
    int4 rg2 = __ldg(&((const int4*)d_rk_g2)[i]);
    int sa[4] = {a.x,a.y,a.z,a.w}, ta[4] = {b.x,b.y,b.z,b.w};
    int sc[4] = {c.x,c.y,c.z,c.w}, tc[4] = {e.x,e.y,e.z,e.w};
    int kc1[4] = {rc1.x,rc1.y,rc1.z,rc1.w}, kg1[4] = {rg1.x,rg1.y,rg1.z,rg1.w};
    int kc2[4] = {rc2.x,rc2.y,rc2.z,rc2.w}, kg2[4] = {rg2.x,rg2.y,rg2.z,rg2.w};
    #pragma unroll
    for (int k = 0; k < 4; k++) {
        d_csr_c1[__ldg(&d_off_c1[sa[k]]) + kc1[k]] = ta[k];
        d_csr_g1[__ldg(&d_off_g1[ta[k]]) + kg1[k]] = sa[k];
        d_csr_c2[__ldg(&d_off_c2[sc[k]]) + kc2[k]] = tc[k];
        d_csr_g2[__ldg(&d_off_g2[tc[k]]) + kg2[k]] = sc[k];
    }
}

// init: fp32 accumulators + pre-scaled fp16 layer-0 tables
__global__ void scale_init_kernel(const float4* __restrict__ cf1,
                                  const float4* __restrict__ cf2,
                                  const float4* __restrict__ gf) {
    int i = blockIdx.x * blockDim.x + threadIdx.x;
    if (i < NC*16) {
        int row = i >> 4;
        float4 x1 = __ldg(&cf1[i]), x2 = __ldg(&cf2[i]);
        float w1 = __ldg(&d_cj1[row]), w2 = __ldg(&d_cj2[row]);
        ((float4*)d_u1)[i] = make_float4(W3*x1.x, W3*x1.y, W3*x1.z, W3*x1.w);
        ((float4*)d_u2)[i] = make_float4(W3*x2.x, W3*x2.y, W3*x2.z, W3*x2.w);
        ((__half2*)d_s1a)[2*i]   = __floats2half2_rn(w1*x1.x, w1*x1.y);
        ((__half2*)d_s1a)[2*i+1] = __floats2half2_rn(w1*x1.z, w1*x1.w);
        ((__half2*)d_s2a)[2*i]   = __floats2half2_rn(w2*x2.x, w2*x2.y);
        ((__half2*)d_s2a)[2*i+1] = __floats2half2_rn(w2*x2.z, w2*x2.w);
    }
    if (i < NG*16) {
        int row = i >> 4;
        float4 g = __ldg(&gf[i]);
        float w1 = __ldg(&d_ci1[row]), w2 = __ldg(&d_ci2[row]);
        ((float4*)d_ih)[i] = make_float4(W3*g.x, W3*g.y, W3*g.z, W3*g.w);
        ((__half2*)d_sg1a)[2*i]   = __floats2half2_rn(w1*g.x, w1*g.y);
        ((__half2*)d_sg1a)[2*i+1] = __floats2half2_rn(w1*g.z, w1*g.w);
        ((__half2*)d_sg2a)[2*i]   = __floats2half2_rn(w2*g.x, w2*g.y);
        ((__half2*)d_sg2a)[2*i+1] = __floats2half2_rn(w2*g.z, w2*g.w);
    }
}

// ---------------- gather: 4 rows / warp-iteration ---------------------------
// Warp split into 4 groups of 8 lanes; group g fetches row j0+g, lane il loads
// uint4 #il (halves il*8..il*8+8). HADD2 accumulate, fp32 spill every <=16 rows.
// facc[k] = partial sum of dim il*8+k over rows of this group.
__device__ __forceinline__ void gather_rows4(const uint4* __restrict__ C,
                                             const int* __restrict__ csr,
                                             int beg, int cnt, int start, int step,
                                             int dummy, int lane, float* facc) {
    const int grp = lane >> 3, il = lane & 7;
    const __half2 z = __float2half2_rn(0.f);
    for (int base = start; base < cnt; base += step) {
        int p = base + lane;
        int idx = (p < cnt) ? __ldg(&csr[beg + p]) : dummy;
        int m = min(32, cnt - base);
        #pragma unroll
        for (int h16 = 0; h16 < 2; h16++) {
            if (h16*16 >= m) break;
            __half2 a0 = z, a1 = z, a2 = z, a3 = z;
            #pragma unroll
            for (int j = 0; j < 16; j += 4) {
                int jj = h16*16 + j;
                if (jj >= m) break;
                int bi = __shfl_sync(0xffffffffu, idx, jj + grp);
                uint4 r = __ldg(&C[bi*8 + il]);
                const __half2* h = (const __half2*)&r;
                a0 = __hadd2(a0, h[0]); a1 = __hadd2(a1, h[1]);
                a2 = __hadd2(a2, h[2]); a3 = __hadd2(a3, h[3]);
            }
            float2 f;
            f = __half22float2(a0); facc[0] += f.x; facc[1] += f.y;
            f = __half22float2(a1); facc[2] += f.x; facc[3] += f.y;
            f = __half22float2(a2); facc[4] += f.x; facc[5] += f.y;
            f = __half22float2(a3); facc[6] += f.x; facc[7] += f.y;
        }
    }
    // reduce across the 4 groups: after this, every lane holds full sums for its il
    #pragma unroll
    for (int k = 0; k < 8; k++) {
        facc[k] += __shfl_xor_sync(0xffffffffu, facc[k], 8);
        facc[k] += __shfl_xor_sync(0xffffffffu, facc[k], 16);
    }
}

// ---------------- fused per-layer SpMM --------------------------------------
// blocks [0, NGB): 2 genes each (4 warps/gene: 2 rel x 2 halves)
// blocks [NGB, ..): 4 cells each (2 warps/cell: 1 per rel)
__global__ void layer_kernel(int layer) {
    const int tid  = threadIdx.x;
    const int lane = tid & 31;
    const int il   = lane & 7;

    if (blockIdx.x < NGB) {
        const uint4* C1 = layer ? d_s1b : d_s1a;
        const uint4* C2 = layer ? d_s2b : d_s2a;
        const int gl   = tid >> 7;
        const int g    = blockIdx.x * 2 + gl;
        const int lw   = (tid >> 5) & 3;
        const int rel  = lw >> 1;
        const int half = lw & 1;

        const int*   csr = rel ? d_csr_g2 : d_csr_g1;
        const uint4* C   = rel ? C2       : C1;
        const int beg = rel ? d_off_g2[g]  : d_off_g1[g];
        const int cnt = rel ? d_deg_dst2[g]: d_deg_dst1[g];

        float facc[8] = {0,0,0,0,0,0,0,0};
        gather_rows4(C, csr, beg, cnt, half * 32, 64, NC, lane, facc);

        __shared__ float part[8][64];
        if (lane < 8) {
            #pragma unroll
            for (int k = 0; k < 8; k++) part[tid >> 5][il*8 + k] = facc[k];
        }
        __syncthreads();
        if ((tid & 127) < 64) {
            int d = tid & 63;
            float p0 = part[gl*4+0][d], p1 = part[gl*4+1][d];
            float p2 = part[gl*4+2][d], p3 = part[gl*4+3][d];
            float c1s = d_ci1[g], c2s = d_ci2[g];
            float go = 0.5f * (c1s * (p0 + p1) + c2s * (p2 + p3));
            float ih = d_ih[g*64 + d] + W3 * go;
            d_ih[g*64 + d] = ih;
            if (!layer) {
                ((__half*)d_sg1b)[g*64 + d] = __float2half(c1s * go);
                ((__half*)d_sg2b)[g*64 + d] = __float2half(c2s * go);
            } else {
                ((__half*)d_ihh)[g*64 + d] = __float2half(ih);
            }
        }
    } else {
        const uint4* G1 = layer ? d_sg1b : d_sg1a;
        const uint4* G2 = layer ? d_sg2b : d_sg2a;
        const int c   = (blockIdx.x - NGB) * 4 + (tid >> 6);
        const int rel = (tid >> 5) & 1;
        const int lane32 = tid & 31;
        if (c >= NC) return;

        const int*   csr = rel ? d_csr_c2 : d_csr_c1;
        const uint4* G   = rel ? G2       : G1;
        const int beg = rel ? d_off_c2[c]  : d_off_c1[c];
        const int cnt = rel ? d_deg_src2[c]: d_deg_src1[c];

        float facc[8] = {0,0,0,0,0,0,0,0};
        gather_rows4(G, csr, beg, cnt, 0, 32, NG, lane32, facc);

        if (lane32 < 8) {
            float s = rel ? d_cj2[c] : d_cj1[c];
            float v[8];
            #pragma unroll
            for (int k = 0; k < 8; k++) v[k] = s * facc[k];
            float* u = (rel ? d_u2 : d_u1) + c*64 + il*8;
            float4 u0 = ((float4*)u)[0], u1 = ((float4*)u)[1];
            u0.x += W3*v[0]; u0.y += W3*v[1]; u0.z += W3*v[2]; u0.w += W3*v[3];
            u1.x += W3*v[4]; u1.y += W3*v[5]; u1.z += W3*v[6]; u1.w += W3*v[7];
            ((float4*)u)[0] = u0; ((float4*)u)[1] = u1;
            if (!layer) {  // next-layer gene input: cj * new cell features
                uint4 pk;
                __half2* ph = (__half2*)&pk;
                ph[0] = __floats2half2_rn(s*v[0], s*v[1]);
                ph[1] = __floats2half2_rn(s*v[2], s*v[3]);
                ph[2] = __floats2half2_rn(s*v[4], s*v[5]);
                ph[3] = __floats2half2_rn(s*v[6], s*v[7]);
                (rel ? d_s2b : d_s1b)[c*8 + il] = pk;
            }
        }
    }
}

// ---------------- embed: y = ELU(BN(u @ W[:64] + b + W[64+branch])) --------
__global__ void emb_kernel(const float* __restrict__ Wm, const float* __restrict__ bb,
                           const float* __restrict__ gam, const float* __restrict__ bet,
                           const float* __restrict__ mu,  const float* __restrict__ var) {
    const int branch = blockIdx.y;
    const float* __restrict__ U = branch ? d_u2 : d_u1;
    __half* __restrict__ UF     = branch ? (__half*)d_ufh2 : (__half*)d_ufh1;

    __shared__ float sU[64][65];
    __shared__ float sW[64][64];
    int tid = threadIdx.x;
    int row0 = blockIdx.x * 64;

    for (int t = tid; t < 64*64; t += 256) sW[t/64][t%64] = Wm[t];
    for (int t = tid; t < 64*64; t += 256) {
        int r = t / 64, k = t % 64;
        int gr = row0 + r;
        sU[r][k] = (gr < NC) ? U[gr*D + k] : 0.f;
    }
    __syncthreads();

    int c  = tid & 63;
    int rq = tid >> 6;
    float acc[16];
    #pragma unroll
    for (int rr = 0; rr < 16; rr++) acc[rr] = 0.f;
    #pragma unroll 8
    for (int k = 0; k < 64; k++) {
        float w = sW[k][c];
        #pragma unroll
        for (int rr = 0; rr < 16; rr++)
            acc[rr] = fmaf(sU[rq*16 + rr][k], w, acc[rr]);
    }
    float scale = gam[c] * rsqrtf(var[c] + BN_EPS);
    float shift = bet[c] - mu[c] * scale;
    float beff  = bb[c] + Wm[(64 + branch)*64 + c];
    #pragma unroll
    for (int rr = 0; rr < 16; rr++) {
        int r = row0 + rq*16 + rr;
        if (r < NC) {
            float y = (acc[rr] + beff) * scale + shift;
            UF[r*D + c] = __float2half(y > 0.f ? y : expm1f(y));
        }
    }
}

// ---------------- decoder: 8 lanes per edge, fp16 rows ----------------------
__global__ void dot_kernel(const int* __restrict__ ps1, const int* __restrict__ pd1,
                           const int* __restrict__ ps2, const int* __restrict__ pd2,
                           float* __restrict__ out) {
    int t = blockIdx.x * blockDim.x + threadIdx.x;
    int e = t >> 3;
    int l = t & 7;
    if (e >= 2*NP) return;
    const uint4* uf; int s, d;
    if (e < NP) { uf = d_ufh1; s = __ldg(&ps1[e]); d = __ldg(&pd1[e]); }
    else { int e2 = e - NP; uf = d_ufh2; s = __ldg(&ps2[e2]); d = __ldg(&pd2[e2]); }
    uint4 A = __ldg(&uf[s*8 + l]);
    uint4 B = __ldg(&d_ihh[d*8 + l]);
    const __half2* ha = (const __half2*)&A;
    const __half2* hb = (const __half2*)&B;
    float v = 0.f;
    #pragma unroll
    for (int k = 0; k < 4; k++) {
        float2 f = __half22float2(__hmul2(ha[k], hb[k]));
        v += f.x + f.y;
    }
    v += __shfl_xor_sync(0xffffffffu, v, 4);
    v += __shfl_xor_sync(0xffffffffu, v, 2);
    v += __shfl_xor_sync(0xffffffffu, v, 1);
    if (l == 0) out[e] = v;
}

// ---------------- host ------------------------------------------------------
extern "C" void kernel_launch(void* const* d_in, const int* in_sizes, int n_in,
                              void* d_out, int out_size) {
    const float* cf1 = (const float*)d_in[0];
    const float* cf2 = (const float*)d_in[1];
    const float* gf  = (const float*)d_in[2];
    const float* Wm  = (const float*)d_in[3];
    const float* bb  = (const float*)d_in[4];
    const float* gam = (const float*)d_in[5];
    const float* bet = (const float*)d_in[6];
    const float* mu  = (const float*)d_in[7];
    const float* var = (const float*)d_in[8];
    const int* es1 = (const int*)d_in[9];
    const int* ed1 = (const int*)d_in[10];
    const int* es2 = (const int*)d_in[11];
    const int* ed2 = (const int*)d_in[12];
    const int* ps1 = (const int*)d_in[13];
    const int* pd1 = (const int*)d_in[14];
    const int* ps2 = (const int*)d_in[15];
    const int* pd2 = (const int*)d_in[16];
    float* out = (float*)d_out;

    zero_kernel   <<<(NC + 255)/256, 256>>>();
    hist_kernel   <<<(NE/4 + 255)/256, 256>>>((const int4*)es1, (const int4*)ed1,
                                              (const int4*)es2, (const int4*)ed2);
    prep_kernel   <<<(NC + 255)/256, 256>>>();
    scatter_kernel<<<(NE/4 + 255)/256, 256>>>((const int4*)es1, (const int4*)ed1,
                                              (const int4*)es2, (const int4*)ed2);
    scale_init_kernel<<<(NC*16 + 255)/256, 256>>>((const float4*)cf1, (const float4*)cf2,
                                                  (const float4*)gf);

    layer_kernel<<<NGB + NCB, 256>>>(0);
    layer_kernel<<<NGB + NCB, 256>>>(1);

    emb_kernel<<<dim3((NC + 63)/64, 2), 256>>>(Wm, bb, gam, bet, mu, var);
    dot_kernel<<<(2*NP*8 + 255)/256, 256>>>(ps1, pd1, ps2, pd2, out);
}